// round 10
// baseline (speedup 1.0000x reference)
#include <cuda_runtime.h>
#include <cuda_bf16.h>

#define EMBED 32
#define NPW 8                 // nodes per warp
#define WARPS_PER_BLOCK 8
#define THREADS 256
#define NODES_PER_BLOCK (WARPS_PER_BLOCK * NPW)   // 64

// f32x2 packed FMA: acc.{lo,hi} += a.{lo,hi} * b.{lo,hi}
#define FFMA2(acc, av, bv) \
    asm("fma.rn.f32x2 %0, %1, %2, %0;" : "+l"(acc) : "l"(av), "l"(bv))

__global__ __launch_bounds__(THREADS)
void agg_kernel(const int* __restrict__ nodes,
                const int* __restrict__ glist,
                const int* __restrict__ alist,
                const float* __restrict__ u_emb,
                const float* __restrict__ g_emb,
                const float* __restrict__ a_emb,
                const float* __restrict__ W,
                const float* __restrict__ b,
                float* __restrict__ out,
                int n) {
    // Persistent shared:
    __shared__ float2 wtp[16 * 33];      // wtp[p*33+j] = {W[j][64+2p], W[j][64+2p+1]}  (k-pairs)
    __shared__ float  gam[16 * EMBED];   // combined gender/age table (incl. bias)
    __shared__ int    ids[NODES_PER_BLOCK];
    // Union region: table-staging (2464 floats) first, then reused as xs (2048 floats).
    __shared__ __align__(16) float un[2464];
    // staging layout: Wt64 = un[0..2112)  (Wt64[k*33+j] = W[j*96+k], k<64)
    //                 ges  = un[2112..2176), aes = un[2176..2432), bs = un[2432..2464)

    const int t    = threadIdx.x;
    const int lane = t & 31;
    const int wib  = t >> 5;
    const long gbase = (long)blockIdx.x * NODES_PER_BLOCK;

    // ---- stage W cols 0..63 transposed, small tables, Wu pairs, node ids ----
    for (int e = t; e < 32 * 64; e += THREADS) {
        int j = e >> 6, k = e & 63;                 // k fastest -> coalesced
        un[k * 33 + j] = W[j * 96 + k];
    }
    if (t < 64) un[2112 + t] = g_emb[t];
    un[2176 + t] = a_emb[t];                        // exactly 256 entries
    if (t < 32) un[2432 + t] = b[t];
    #pragma unroll
    for (int e = t; e < 512; e += THREADS) {
        int j = e >> 4, p = e & 15;
        wtp[p * 33 + j] = *(const float2*)&W[j * 96 + 64 + 2 * p];  // 8B aligned
    }
    if (t < NODES_PER_BLOCK) {
        long idx = gbase + t;
        ids[t] = (idx < n) ? nodes[idx] : 0;
    }
    __syncthreads();

    // ---- per-block gamat table: 512 entries, 2 per thread, 64 FMA each ----
    #pragma unroll
    for (int r = 0; r < 2; r++) {
        int e  = t + r * THREADS;                   // 0..511
        int j  = e & 31;
        int ga = e >> 5;
        int g  = ga >> 3, a = ga & 7;
        float acc = un[2432 + j];
        #pragma unroll
        for (int k = 0; k < 32; k++) acc += un[2112 + g * 32 + k] * un[k * 33 + j];
        #pragma unroll
        for (int k = 0; k < 32; k++) acc += un[2176 + a * 32 + k] * un[(32 + k) * 33 + j];
        gam[ga * EMBED + j] = acc;
    }
    __syncthreads();        // gam/wtp ready; staging region now dead -> reuse as xs

    float* xs = un;         // xs[(wib*NPW + i)*EMBED + lane]

    const long base = gbase + (long)wib * NPW;
    if (base < n) {
        // Node ids (broadcast LDS).
        int node[NPW];
        #pragma unroll
        for (int i = 0; i < NPW; i++) node[i] = ids[wib * NPW + i];

        // Batched random 4B gathers: 16 independent loads in flight.
        int g[NPW], a[NPW];
        #pragma unroll
        for (int i = 0; i < NPW; i++) {
            g[i] = __ldg(&glist[node[i]]);
            a[i] = __ldg(&alist[node[i]]);
        }

        // u_emb row gather, float4: 4 rows per pass (8 lanes/row), 2 passes.
        #pragma unroll
        for (int pass = 0; pass < 2; pass++) {
            int i  = pass * 4 + (lane >> 3);        // row within warp's 8 nodes
            int q  = lane & 7;                      // float4 index within row
            int nd = ids[wib * NPW + i];
            float4 v = __ldg((const float4*)&u_emb[(long)nd * EMBED] + q);
            *((float4*)&xs[(wib * NPW + i) * EMBED] + q) = v;
        }

        // Init packed accumulators: lo = table value, hi = 0.
        unsigned long long acc2[NPW];
        #pragma unroll
        for (int i = 0; i < NPW; i++) {
            float ginit = gam[((g[i] << 3) + a[i]) * EMBED + lane];
            asm("mov.b64 %0, {%1, %2};" : "=l"(acc2[i]) : "f"(ginit), "f"(0.0f));
        }

        __syncwarp();

        // Packed matvec: lane j computes out[node][j]. k packed in pairs:
        // x pairs come directly from LDS.128 (ulonglong2), w pairs from wtp
        // (LDS.64). 128 FFMA2 per lane instead of 256 FFMA.
        #pragma unroll
        for (int c = 0; c < 4; c++) {
            unsigned long long wq[4];
            #pragma unroll
            for (int q = 0; q < 4; q++)
                wq[q] = *(const unsigned long long*)&wtp[(c * 4 + q) * 33 + lane];
            #pragma unroll
            for (int i = 0; i < NPW; i++) {
                const float* xrow = &xs[(wib * NPW + i) * EMBED + c * 8];
                ulonglong2 xv0 = *(const ulonglong2*)(xrow);        // pairs (k,k+1),(k+2,k+3)
                ulonglong2 xv1 = *(const ulonglong2*)(xrow + 4);
                FFMA2(acc2[i], xv0.x, wq[0]);
                FFMA2(acc2[i], xv0.y, wq[1]);
                FFMA2(acc2[i], xv1.x, wq[2]);
                FFMA2(acc2[i], xv1.y, wq[3]);
            }
        }

        // Epilogue: fold even/odd halves, ReLU, store.
        #pragma unroll
        for (int i = 0; i < NPW; i++) {
            long idx = base + i;
            if (idx < n) {
                float lo, hi;
                asm("mov.b64 {%0, %1}, %2;" : "=f"(lo), "=f"(hi) : "l"(acc2[i]));
                out[idx * EMBED + lane] = fmaxf(lo + hi, 0.f);
            }
        }
    }
}

extern "C" void kernel_launch(void* const* d_in, const int* in_sizes, int n_in,
                              void* d_out, int out_size) {
    const int*   nodes = (const int*)d_in[0];
    const int*   glist = (const int*)d_in[1];
    const int*   alist = (const int*)d_in[2];
    const float* u_emb = (const float*)d_in[3];
    const float* g_emb = (const float*)d_in[4];
    const float* a_emb = (const float*)d_in[5];
    const float* W     = (const float*)d_in[6];
    const float* b     = (const float*)d_in[7];
    float* out = (float*)d_out;
    int n = in_sizes[0];

    int blocks = (n + NODES_PER_BLOCK - 1) / NODES_PER_BLOCK;
    agg_kernel<<<blocks, THREADS>>>(nodes, glist, alist, u_emb, g_emb, a_emb, W, b, out, n);
}